// round 7
// baseline (speedup 1.0000x reference)
#include <cuda_runtime.h>
#include <cstdint>

// Problem constants
#define BB 4
#define LL 4096
#define DD 768
#define CH 256            // chunks per batch
#define CROWS 16          // rows per chunk
#define RBLK 256          // reader blocks (each loops over batches in order)
#define CTXB 32           // ctx blocks (reduce + gemv), dispatched after readers
#define OPB 24            // ctx outputs per block (32*24 = 768)
#define SPAN 32           // rows per bcast block

// Scratch + flags (device globals)
__device__ float g_partial[CH][BB][DD];
__device__ float g_wsum[CH][BB];
__device__ float g_hbar[BB][DD];
__device__ float g_ctx[BB][DD];
__device__ int   g_done[BB];     // reader chunks finished per batch
__device__ int   g_hdone[BB];    // ctx blocks past hbar stage
__device__ int   g_cdone[BB];    // ctx blocks past gemv stage (ctx[b] final)
__device__ float g_sink;

__global__ void reset_kernel() {
    if (threadIdx.x < BB) {
        g_done[threadIdx.x] = 0; g_hdone[threadIdx.x] = 0; g_cdone[threadIdx.x] = 0;
    }
}

__device__ __forceinline__ void spin_ge(const int* p, int target) {
    while (*(volatile const int*)p < target) __nanosleep(64);
}

// ---------------------------------------------------------------------------
// Kernel 1: readers (wsum, batches in order) + ctx blocks (reduce + gemv).
// Triggers programmatic launch completion at entry so bcast co-resides.
// mask is {0,-1e9} => weights exactly {1,0}: dead rows skipped; softmax
// normalization deferred (divide by total weight in hbar stage).
// ---------------------------------------------------------------------------
__global__ void __launch_bounds__(192) wsum_ctx_kernel(
    const float* __restrict__ hs, const float* __restrict__ mask,
    const float* __restrict__ Wv, const float* __restrict__ bv)
{
#if __CUDA_ARCH__ >= 900
    cudaTriggerProgrammaticLaunchCompletion();
#endif
    const int B = blockIdx.x;
    const int t = threadIdx.x;                 // 192 = DD/4

    if (B < RBLK) {
        // ---------------- READER: one chunk, batches in order --------------
        __shared__ float p[CROWS];
        const int c = B;
        for (int b = 0; b < BB; b++) {
            if (t < CROWS) {                   // lanes 0..15 of warp 0
                float w = expf(__ldg(&mask[(size_t)b * LL + c * CROWS + t]));
                p[t] = w;
                #pragma unroll
                for (int o = 8; o > 0; o >>= 1)
                    w += __shfl_down_sync(0x0000ffffu, w, o, 16);
                if (t == 0) g_wsum[c][b] = w;
            }
            __syncthreads();

            const float4* __restrict__ src =
                (const float4*)(hs + ((size_t)b * LL + (size_t)c * CROWS) * DD);
            float4 acc = make_float4(0.f, 0.f, 0.f, 0.f);
            #pragma unroll
            for (int r = 0; r < CROWS; r++) {
                const float pr = p[r];
                if (pr != 0.0f) {              // uniform branch: skip dead rows
                    const float4 x = src[(size_t)r * (DD / 4) + t];
                    acc.x = fmaf(pr, x.x, acc.x);
                    acc.y = fmaf(pr, x.y, acc.y);
                    acc.z = fmaf(pr, x.z, acc.z);
                    acc.w = fmaf(pr, x.w, acc.w);
                }
            }
            ((float4*)g_partial[c][b])[t] = acc;
            __threadfence();
            __syncthreads();                   // all stores fenced; p reusable
            if (t == 0) atomicAdd(&g_done[b], 1);
        }
        return;
    }

    // ---------------- CTX: reduce + gemv per batch -------------------------
    const int j = B - RBLK;                    // 0..CTXB-1
    __shared__ float  s_invw;
    __shared__ float4 s_h4[DD / 4];
    {   // warm Wv into L2 while readers stream
        const float4* __restrict__ w4 = (const float4*)Wv;
        float a = 0.f;
        #pragma unroll
        for (int i = 0; i < 24; i++) {         // 24*CTXB*192 = DD*DD/4
            const float4 v = __ldg(&w4[(j * 192 + t) + i * (CTXB * 192)]);
            a += v.x + v.y + v.z + v.w;
        }
        if (a == 1.23456789e30f) g_sink = a;   // never true; defeats DCE
    }
    const int o0 = j * OPB;
    for (int b = 0; b < BB; b++) {
        if (t == 0) spin_ge(&g_done[b], RBLK);
        __syncthreads();
        __threadfence();
        if (t < 32) {                          // total weight -> 1/sum
            float s = 0.f;                     // __ldcg: wsum lines span batches
            #pragma unroll
            for (int i = 0; i < CH / 32; i++) s += __ldcg(&g_wsum[t + 32 * i][b]);
            #pragma unroll
            for (int o = 16; o > 0; o >>= 1) s += __shfl_down_sync(0xffffffffu, s, o);
            if (t == 0) s_invw = 1.0f / s;
        }
        __syncthreads();
        {   // hbar: 24 outputs, 8 threads each (32 chunks per thread)
            const int g8 = t >> 3, sub = t & 7;
            const int o = o0 + g8;
            float s = 0.f;
            #pragma unroll 8
            for (int k = 0; k < CH / 8; k++)
                s += __ldcg(&g_partial[sub * (CH / 8) + k][b][o]);
            #pragma unroll
            for (int off = 4; off > 0; off >>= 1)
                s += __shfl_down_sync(0xffffffffu, s, off, 8);
            if (sub == 0) g_hbar[b][o] = s * s_invw;
        }
        __threadfence();
        __syncthreads();
        if (t == 0) { atomicAdd(&g_hdone[b], 1); spin_ge(&g_hdone[b], CTXB); }
        __syncthreads();
        __threadfence();
        s_h4[t] = __ldcg(&((const float4*)g_hbar[b])[t]);   // full hbar row
        __syncthreads();
        {   // gemv: 6 warps x 4 outputs each (Wv L2-warm)
            const int w = t >> 5, lane = t & 31;
            for (int o = o0 + w; o < o0 + OPB; o += 6) {
                const float4* __restrict__ wv4 = (const float4*)(Wv + (size_t)o * DD);
                float acc = 0.f;
                #pragma unroll
                for (int i = 0; i < 6; i++) {
                    const float4 wv = __ldg(&wv4[lane + 32 * i]);
                    const float4 hv = s_h4[lane + 32 * i];
                    acc = fmaf(wv.x, hv.x, fmaf(wv.y, hv.y,
                          fmaf(wv.z, hv.z, fmaf(wv.w, hv.w, acc))));
                }
                #pragma unroll
                for (int off = 16; off > 0; off >>= 1)
                    acc += __shfl_down_sync(0xffffffffu, acc, off);
                if (lane == 0) g_ctx[b][o] = acc + __ldg(&bv[o]);
            }
        }
        __threadfence();
        __syncthreads();
        if (t == 0) atomicAdd(&g_cdone[b], 1);
    }
}

// ---------------------------------------------------------------------------
// Kernel 2: bcast. Launched with PSS (co-resides with wsum_ctx thanks to its
// early trigger); NO gridDependencySynchronize — correctness via cdone flags.
// Batch-0 writes start while later batches are still being read.
// ---------------------------------------------------------------------------
__global__ void __launch_bounds__(192) bcast_kernel(float* __restrict__ out) {
    const int b = blockIdx.y;
    const int t = threadIdx.x;                 // 192 = DD/4

    if (t == 0) spin_ge(&g_cdone[b], CTXB);
    __syncthreads();
    __threadfence();
    const float4 v = __ldcg(&((const float4*)g_ctx[b])[t]);

    float4* __restrict__ dst =
        (float4*)(out + ((size_t)b * LL + (size_t)blockIdx.x * SPAN) * DD);
    #pragma unroll
    for (int r = 0; r < SPAN; r++)
        dst[(size_t)r * (DD / 4) + t] = v;
}

// ---------------------------------------------------------------------------
template <typename K, typename... Args>
static inline void launch_pdl(K kern, dim3 grid, dim3 block, Args... args) {
    cudaLaunchConfig_t cfg = {};
    cfg.gridDim = grid;
    cfg.blockDim = block;
    cudaLaunchAttribute attr[1];
    attr[0].id = cudaLaunchAttributeProgrammaticStreamSerialization;
    attr[0].val.programmaticStreamSerializationAllowed = 1;
    cfg.attrs = attr;
    cfg.numAttrs = 1;
    cudaLaunchKernelEx(&cfg, kern, args...);
}

// ---------------------------------------------------------------------------
// Inputs: hidden_states, attention_mask, Wq, bq, Wk, bk, Wv, bv (Q/K dead)
// ---------------------------------------------------------------------------
extern "C" void kernel_launch(void* const* d_in, const int* in_sizes, int n_in,
                              void* d_out, int out_size) {
    const float* hs   = (const float*)d_in[0];
    const float* mask = (const float*)d_in[1];
    const float* Wv   = (const float*)d_in[6];
    const float* bv   = (const float*)d_in[7];
    float* out = (float*)d_out;

    reset_kernel<<<1, 32>>>();
    wsum_ctx_kernel<<<RBLK + CTXB, 192>>>(hs, mask, Wv, bv);
    launch_pdl(bcast_kernel, dim3(LL / SPAN, BB), dim3(192), out);
}

// round 8
// speedup vs baseline: 2.2484x; 2.2484x over previous
#include <cuda_runtime.h>
#include <cstdint>

// Problem constants
#define BB 4
#define LL 4096
#define DD 768
#define CHUNKS 256
#define ROWS 16            // LL / CHUNKS
#define PF 48              // Wv L2-prefetch blocks riding on wsum launch
#define KSPL 4             // gemv split-K factor
#define KS (DD / KSPL)     // 192 k-elements per slice
#define SPAN 16            // output rows per bcast block (R2 best: 11.33us)

// Scratch (device globals — no allocations allowed)
__device__ float g_partial[CHUNKS][BB][DD];   // per-chunk exp-weighted sums
__device__ float g_wsum[CHUNKS][BB];          // per-chunk exp-weight sums
__device__ float g_hbar[BB][DD];              // normalized probs·hs
__device__ float g_ctx[BB][DD];               // final context row (bias folded)
__device__ float g_sink;                      // DCE defeat for prefetch

// ---------------------------------------------------------------------------
// 1) wsum: partial[c][b][:] = Σ_{l in chunk, w(l)!=0} exp(mask[b,l])*hs[b,l,:]
//    mask is {0, -1e9} so weights are exactly {1, 0}: zero-weight rows are
//    SKIPPED (block-uniform branch). Blocks x >= CHUNKS prefetch Wv into L2.
// ---------------------------------------------------------------------------
__global__ void __launch_bounds__(192) wsum_kernel(const float* __restrict__ hs,
                                                   const float* __restrict__ mask,
                                                   const float* __restrict__ Wv) {
    const int t = threadIdx.x;                 // 192 = DD/4

    if (blockIdx.x >= CHUNKS) {                // Wv prefetch blocks
        if (blockIdx.y != 0) return;
        const int pb = blockIdx.x - CHUNKS;    // 0..PF-1
        const float4* __restrict__ w4 = (const float4*)Wv;
        float acc = 0.0f;
        #pragma unroll
        for (int i = 0; i < 16; i++) {         // PF*192*16 = DD*DD/4
            const float4 v = __ldg(&w4[(size_t)pb * (16 * 192) + i * 192 + t]);
            acc += v.x + v.y + v.z + v.w;
        }
        if (acc == 1.23456789e30f) g_sink = acc;   // never true; defeats DCE
        return;
    }

    const int c = blockIdx.x;
    const int b = blockIdx.y;

    __shared__ float p[ROWS];
    if (t < ROWS) {                            // lanes 0..15 of warp 0
        float w = expf(__ldg(&mask[(size_t)b * LL + c * ROWS + t]));
        p[t] = w;
        #pragma unroll
        for (int o = 8; o > 0; o >>= 1) w += __shfl_down_sync(0x0000ffffu, w, o, 16);
        if (t == 0) g_wsum[c][b] = w;
    }
    __syncthreads();

    const float4* __restrict__ src =
        (const float4*)(hs + ((size_t)b * LL + (size_t)c * ROWS) * DD);

    float4 acc = make_float4(0.f, 0.f, 0.f, 0.f);
    #pragma unroll
    for (int r = 0; r < ROWS; r++) {
        const float pr = p[r];
        if (pr != 0.0f) {                      // uniform branch: skip dead rows
            const float4 x = src[(size_t)r * (DD / 4) + t];
            acc.x = fmaf(pr, x.x, acc.x);
            acc.y = fmaf(pr, x.y, acc.y);
            acc.z = fmaf(pr, x.z, acc.z);
            acc.w = fmaf(pr, x.w, acc.w);
        }
    }
    ((float4*)g_partial[c][b])[t] = acc;
}

// ---------------------------------------------------------------------------
// 2) reduce: hbar[b][k] = (Σ_c partial[c][b][k]) / (Σ_c wsum[c][b])
//    48 blocks; each output summed by 4 threads (64 chunks each) + smem fold.
// ---------------------------------------------------------------------------
__global__ void __launch_bounds__(256) reduce_kernel() {
#if __CUDA_ARCH__ >= 900
    cudaGridDependencySynchronize();           // PDL: wait for wsum's writes
#endif
    __shared__ float invw[BB];
    __shared__ float sm[256];
    const int t = threadIdx.x;
    const int wid = t >> 5, lane = t & 31;

    if (wid < BB) {                            // warps 0..3: one batch each
        float s = 0.0f;
        #pragma unroll
        for (int i = 0; i < CHUNKS / 32; i++) s += g_wsum[lane + 32 * i][wid];
        #pragma unroll
        for (int o = 16; o > 0; o >>= 1) s += __shfl_down_sync(0xffffffffu, s, o);
        if (lane == 0) invw[wid] = 1.0f / s;
    }
    __syncthreads();

    const int g  = t >> 6;                     // chunk group 0..3 (64 chunks each)
    const int ol = t & 63;                     // local output 0..63
    {
        const int o = blockIdx.x * 64 + ol;    // 0..3071
        const int b = o / DD, k = o % DD;
        float s = 0.0f;
        #pragma unroll 8
        for (int c = g * 64; c < (g + 1) * 64; c++) s += g_partial[c][b][k];
        sm[t] = s;
    }
    __syncthreads();
    if (t < 64) {
        const int o = blockIdx.x * 64 + t;
        const int b = o / DD, k = o % DD;
        g_hbar[b][k] = (sm[t] + sm[t + 64] + sm[t + 128] + sm[t + 192]) * invw[b];
    }
}

// ---------------------------------------------------------------------------
// 3) gemv: ctx[b][d] = hbar[b,:]·Wv[d,:] + bv[d]
//    8 warps/block = 2 outputs x 4 k-slices; slice combine in smem.
// ---------------------------------------------------------------------------
__global__ void __launch_bounds__(256) gemv_kernel(const float* __restrict__ Wv,
                                                   const float* __restrict__ bv) {
#if __CUDA_ARCH__ >= 900
    cudaGridDependencySynchronize();           // PDL: wait for reduce's writes
#endif
    __shared__ float part[8];
    const int w    = threadIdx.x >> 5;         // 0..7
    const int lane = threadIdx.x & 31;
    const int oidx = blockIdx.x * 2 + (w >> 2);  // 0..3071
    const int s    = w & 3;
    const int b    = oidx / DD, d = oidx % DD;

    const float2* __restrict__ h2 = (const float2*)(g_hbar[b]) + s * (KS / 2);
    const float2* __restrict__ w2 = (const float2*)(Wv + (size_t)d * DD) + s * (KS / 2);

    float acc = 0.0f;
    #pragma unroll
    for (int i = 0; i < 3; i++) {              // KS/2 = 96 float2 over 32 lanes
        const float2 hv = h2[lane + 32 * i];
        const float2 wv = __ldg(&w2[lane + 32 * i]);
        acc = fmaf(hv.x, wv.x, fmaf(hv.y, wv.y, acc));
    }
    #pragma unroll
    for (int o = 16; o > 0; o >>= 1) acc += __shfl_down_sync(0xffffffffu, acc, o);
    if (lane == 0) part[w] = acc;
    __syncthreads();
    if (threadIdx.x < 2) {
        const int o2 = blockIdx.x * 2 + threadIdx.x;
        const float r = part[threadIdx.x * 4] + part[threadIdx.x * 4 + 1] +
                        part[threadIdx.x * 4 + 2] + part[threadIdx.x * 4 + 3] +
                        __ldg(&bv[o2 % DD]);
        g_ctx[o2 / DD][o2 % DD] = r;
    }
}

// ---------------------------------------------------------------------------
// 4) bcast: out[b,l,:] = ctx[b,:] — R2-best config: scalar float4 STG,
//    16 rows/block, grid (256, BB). __stcs keeps the never-re-read output
//    out of L2 residency (helps hs stay resident across graph replays).
// ---------------------------------------------------------------------------
__global__ void __launch_bounds__(192) bcast_kernel(float* __restrict__ out) {
#if __CUDA_ARCH__ >= 900
    cudaGridDependencySynchronize();           // PDL: wait for gemv's writes
#endif
    const int b = blockIdx.y;
    const int t = threadIdx.x;                 // 192 = DD/4
    const float4 v = __ldg(&((const float4*)g_ctx[b])[t]);

    float4* __restrict__ dst =
        (float4*)(out + ((size_t)b * LL + (size_t)blockIdx.x * SPAN) * DD);
    #pragma unroll
    for (int r = 0; r < SPAN; r++)
        __stcs(&dst[(size_t)r * (DD / 4) + t], v);
}

// ---------------------------------------------------------------------------
// Launch helpers — PDL-attributed launches for the dependent kernels.
// ---------------------------------------------------------------------------
template <typename K, typename... Args>
static inline void launch_pdl(K kern, dim3 grid, dim3 block, Args... args) {
    cudaLaunchConfig_t cfg = {};
    cfg.gridDim = grid;
    cfg.blockDim = block;
    cudaLaunchAttribute attr[1];
    attr[0].id = cudaLaunchAttributeProgrammaticStreamSerialization;
    attr[0].val.programmaticStreamSerializationAllowed = 1;
    cfg.attrs = attr;
    cfg.numAttrs = 1;
    cudaLaunchKernelEx(&cfg, kern, args...);
}

// ---------------------------------------------------------------------------
// Inputs: hidden_states, attention_mask, Wq, bq, Wk, bk, Wv, bv (Q/K dead)
// ---------------------------------------------------------------------------
extern "C" void kernel_launch(void* const* d_in, const int* in_sizes, int n_in,
                              void* d_out, int out_size) {
    const float* hs   = (const float*)d_in[0];
    const float* mask = (const float*)d_in[1];
    const float* Wv   = (const float*)d_in[6];
    const float* bv   = (const float*)d_in[7];
    float* out = (float*)d_out;

    wsum_kernel<<<dim3(CHUNKS + PF, BB), 192>>>(hs, mask, Wv);
    launch_pdl(reduce_kernel, dim3(48), dim3(256));
    launch_pdl(gemv_kernel, dim3((BB * DD) / 2), dim3(256), Wv, bv);
    launch_pdl(bcast_kernel, dim3(LL / SPAN, BB), dim3(192), out);
}